// round 3
// baseline (speedup 1.0000x reference)
#include <cuda_runtime.h>

static constexpr int B = 16, C = 21, H = 512, W = 512;
static constexpr int HW = H * W;            // 262144
static constexpr int NPLANES = B * C;       // 336
static constexpr int P4 = HW / 4;           // 65536 float4 per plane
static constexpr int TPB = 256;
static constexpr int BLOCKS_PER_PLANE = 64;
static constexpr int ITERS = P4 / (TPB * BLOCKS_PER_PLANE); // 4

// Scratch accumulators (no allocation allowed in kernel_launch)
__device__ float g_ta[NPLANES];
__device__ float g_tb[NPLANES];
__device__ float g_inter[NPLANES];

__global__ void zero_kernel() {
    int i = threadIdx.x;
    if (i < NPLANES) {
        g_ta[i] = 0.0f;
        g_tb[i] = 0.0f;
        g_inter[i] = 0.0f;
    }
}

__global__ __launch_bounds__(TPB) void sums_kernel(
    const float4* __restrict__ yp, const float4* __restrict__ yt)
{
    const int plane = blockIdx.x / BLOCKS_PER_PLANE;
    const int seg   = blockIdx.x % BLOCKS_PER_PLANE;
    const size_t base = (size_t)plane * P4 + (size_t)seg * (TPB * ITERS);

    const float4* p = yp + base;
    const float4* t = yt + base;

    float ta = 0.0f, tb = 0.0f, it = 0.0f;
    #pragma unroll
    for (int k = 0; k < ITERS; k++) {
        float4 a = p[threadIdx.x + k * TPB];   // y_pred
        float4 b = t[threadIdx.x + k * TPB];   // y_true
        tb += (a.x + a.y) + (a.z + a.w);
        ta += (b.x + b.y) + (b.z + b.w);
        it += a.x * b.x + a.y * b.y + a.z * b.z + a.w * b.w;
    }

    // warp reduce
    #pragma unroll
    for (int o = 16; o > 0; o >>= 1) {
        ta += __shfl_down_sync(0xFFFFFFFFu, ta, o);
        tb += __shfl_down_sync(0xFFFFFFFFu, tb, o);
        it += __shfl_down_sync(0xFFFFFFFFu, it, o);
    }

    __shared__ float sta[TPB / 32], stb[TPB / 32], sit[TPB / 32];
    int w = threadIdx.x >> 5, l = threadIdx.x & 31;
    if (l == 0) { sta[w] = ta; stb[w] = tb; sit[w] = it; }
    __syncthreads();

    if (threadIdx.x == 0) {
        float A = 0.0f, Bv = 0.0f, I = 0.0f;
        #pragma unroll
        for (int i = 0; i < TPB / 32; i++) { A += sta[i]; Bv += stb[i]; I += sit[i]; }
        atomicAdd(&g_ta[plane], A);
        atomicAdd(&g_tb[plane], Bv);
        atomicAdd(&g_inter[plane], I);
    }
}

__global__ void finalize_kernel(const int* __restrict__ bg_ptr,
                                float* __restrict__ out)
{
    const int bg = *bg_ptr;
    const int b = threadIdx.x;  // one batch per lane, lanes >= B contribute 0

    float tmp = 0.0f;   // per-batch mean dice (or 0)
    float bv  = 0.0f;   // batch_valid as float
    if (b < B) {
        int cnt = 0;
        float sd = 0.0f;
        for (int c = bg; c < C; c++) {
            float ta = g_ta[b * C + c];
            float tb = g_tb[b * C + c];
            float in = g_inter[b * C + c];
            if (ta != 0.0f) {
                cnt++;
                sd += 2.0f * in / (ta + tb + 1e-11f);
            }
        }
        float denom = (float)cnt - (float)bg;   // cpt2 - bg, as in reference
        if (denom != 0.0f) {
            tmp = sd / denom;
            bv = 1.0f;
        }
    }

    #pragma unroll
    for (int o = 16; o > 0; o >>= 1) {
        tmp += __shfl_down_sync(0xFFFFFFFFu, tmp, o);
        bv  += __shfl_down_sync(0xFFFFFFFFu, bv,  o);
    }

    if (threadIdx.x == 0) {
        float cpt1 = bv;
        float loss = 1.0f - tmp / fmaxf(cpt1, 1.0f);
        out[0] = (cpt1 > 0.0f) ? loss : -1.0f;
    }
}

extern "C" void kernel_launch(void* const* d_in, const int* in_sizes, int n_in,
                              void* d_out, int out_size)
{
    const float4* y_pred = (const float4*)d_in[0];
    const float4* y_true = (const float4*)d_in[1];
    const int*    bg     = (const int*)d_in[2];
    float*        out    = (float*)d_out;

    zero_kernel<<<1, 512>>>();
    sums_kernel<<<NPLANES * BLOCKS_PER_PLANE, TPB>>>(y_pred, y_true);
    finalize_kernel<<<1, 32>>>(bg, out);
}

// round 4
// speedup vs baseline: 1.0044x; 1.0044x over previous
#include <cuda_runtime.h>

static constexpr int B = 16, C = 21, H = 512, W = 512;
static constexpr int HW = H * W;            // 262144
static constexpr int NPLANES = B * C;       // 336
static constexpr int P4 = HW / 4;           // 65536 float4 per plane
static constexpr int TPB = 256;
static constexpr int BLOCKS_PER_PLANE = 64;
static constexpr int ITERS = P4 / (TPB * BLOCKS_PER_PLANE); // 4

// Scratch accumulators (no allocation allowed in kernel_launch)
__device__ float g_ta[NPLANES];
__device__ float g_tb[NPLANES];
__device__ float g_inter[NPLANES];

__global__ void zero_kernel() {
    int i = threadIdx.x;
    if (i < NPLANES) {
        g_ta[i] = 0.0f;
        g_tb[i] = 0.0f;
        g_inter[i] = 0.0f;
    }
}

__global__ __launch_bounds__(TPB) void sums_kernel(
    const float4* __restrict__ yp, const float4* __restrict__ yt)
{
    const int plane = blockIdx.x / BLOCKS_PER_PLANE;
    const int seg   = blockIdx.x % BLOCKS_PER_PLANE;
    const size_t base = (size_t)plane * P4 + (size_t)seg * (TPB * ITERS);

    const float4* p = yp + base;
    const float4* t = yt + base;

    float ta = 0.0f, tb = 0.0f, it = 0.0f;
    #pragma unroll
    for (int k = 0; k < ITERS; k++) {
        float4 a = p[threadIdx.x + k * TPB];   // y_pred
        float4 b = t[threadIdx.x + k * TPB];   // y_true
        tb += (a.x + a.y) + (a.z + a.w);
        ta += (b.x + b.y) + (b.z + b.w);
        it += a.x * b.x + a.y * b.y + a.z * b.z + a.w * b.w;
    }

    // warp reduce
    #pragma unroll
    for (int o = 16; o > 0; o >>= 1) {
        ta += __shfl_down_sync(0xFFFFFFFFu, ta, o);
        tb += __shfl_down_sync(0xFFFFFFFFu, tb, o);
        it += __shfl_down_sync(0xFFFFFFFFu, it, o);
    }

    __shared__ float sta[TPB / 32], stb[TPB / 32], sit[TPB / 32];
    int w = threadIdx.x >> 5, l = threadIdx.x & 31;
    if (l == 0) { sta[w] = ta; stb[w] = tb; sit[w] = it; }
    __syncthreads();

    if (threadIdx.x == 0) {
        float A = 0.0f, Bv = 0.0f, I = 0.0f;
        #pragma unroll
        for (int i = 0; i < TPB / 32; i++) { A += sta[i]; Bv += stb[i]; I += sit[i]; }
        atomicAdd(&g_ta[plane], A);
        atomicAdd(&g_tb[plane], Bv);
        atomicAdd(&g_inter[plane], I);
    }
}

__global__ void finalize_kernel(const int* __restrict__ bg_ptr,
                                float* __restrict__ out)
{
    const int bg = *bg_ptr;
    const int b = threadIdx.x;  // one batch per lane, lanes >= B contribute 0

    float tmp = 0.0f;   // per-batch mean dice (or 0)
    float bv  = 0.0f;   // batch_valid as float
    if (b < B) {
        int cnt = 0;
        float sd = 0.0f;
        for (int c = bg; c < C; c++) {
            float ta = g_ta[b * C + c];
            float tb = g_tb[b * C + c];
            float in = g_inter[b * C + c];
            if (ta != 0.0f) {
                cnt++;
                sd += 2.0f * in / (ta + tb + 1e-11f);
            }
        }
        float denom = (float)cnt - (float)bg;   // cpt2 - bg, as in reference
        if (denom != 0.0f) {
            tmp = sd / denom;
            bv = 1.0f;
        }
    }

    #pragma unroll
    for (int o = 16; o > 0; o >>= 1) {
        tmp += __shfl_down_sync(0xFFFFFFFFu, tmp, o);
        bv  += __shfl_down_sync(0xFFFFFFFFu, bv,  o);
    }

    if (threadIdx.x == 0) {
        float cpt1 = bv;
        float loss = 1.0f - tmp / fmaxf(cpt1, 1.0f);
        out[0] = (cpt1 > 0.0f) ? loss : -1.0f;
    }
}

extern "C" void kernel_launch(void* const* d_in, const int* in_sizes, int n_in,
                              void* d_out, int out_size)
{
    const float4* y_pred = (const float4*)d_in[0];
    const float4* y_true = (const float4*)d_in[1];
    const int*    bg     = (const int*)d_in[2];
    float*        out    = (float*)d_out;

    zero_kernel<<<1, 512>>>();
    sums_kernel<<<NPLANES * BLOCKS_PER_PLANE, TPB>>>(y_pred, y_true);
    finalize_kernel<<<1, 32>>>(bg, out);
}